// round 1
// baseline (speedup 1.0000x reference)
#include <cuda_runtime.h>

// Derived scalar constants, computed on-device each launch (deterministic).
// Layout: [0..3] = AB direction {alpha, gamma, K1, R}, [4..7] = BA direction.
__device__ float g_C[8];

// ---------------------------------------------------------------------------
// Setup: 2 warps, one per attention direction. Lane e computes component e of
// the derived vectors, then warp-reduces the needed dot products.
//
//   uq = Wq @ w_q,  cq = Wq @ b_q + bq        (q-side token basis)
//   uk = Wk @ w_k                              (kv-side token basis)
//   uv = Wv @ w_k,  cv = Wv @ b_k + bv
//   g  = Wo^T @ Wf_row
//   alpha = (uq.uk)/sqrt(32), gamma = (cq.uk)/sqrt(32)
//   K1 = 0.5 * g.uv,  R = g.cv + Wf.bo
// ---------------------------------------------------------------------------
__global__ void setup_kernel(
    const float* __restrict__ WA, const float* __restrict__ bA,
    const float* __restrict__ WB, const float* __restrict__ bB,
    const float* __restrict__ Wi_AB, const float* __restrict__ bi_AB,
    const float* __restrict__ Wo_AB, const float* __restrict__ bo_AB,
    const float* __restrict__ Wi_BA, const float* __restrict__ bi_BA,
    const float* __restrict__ Wo_BA, const float* __restrict__ bo_BA,
    const float* __restrict__ Wf)
{
    const int w = threadIdx.x >> 5;   // 0 = AB (q from A, kv from B), 1 = BA
    const int e = threadIdx.x & 31;
    if (w > 1) return;

    const float* Wi = w ? Wi_BA : Wi_AB;
    const float* bi = w ? bi_BA : bi_AB;
    const float* Wo = w ? Wo_BA : Wo_AB;
    const float* bo = w ? bo_BA : bo_AB;
    const float* q_w = w ? WB : WA;  const float* q_b = w ? bB : bA;
    const float* k_w = w ? WA : WB;  const float* k_b = w ? bA : bB;

    float uq = 0.f, cq = 0.f, uk = 0.f, uv = 0.f, cv = 0.f, g = 0.f;
    #pragma unroll
    for (int d = 0; d < 32; ++d) {
        const float wq = Wi[e * 32 + d];
        const float wk = Wi[(32 + e) * 32 + d];
        const float wv = Wi[(64 + e) * 32 + d];
        uq = fmaf(wq, q_w[d], uq);
        cq = fmaf(wq, q_b[d], cq);
        uk = fmaf(wk, k_w[d], uk);
        uv = fmaf(wv, k_w[d], uv);
        cv = fmaf(wv, k_b[d], cv);
        g  = fmaf(Wf[d], Wo[d * 32 + e], g);
    }
    cq += bi[e];        // + bq[e]
    cv += bi[64 + e];   // + bv[e]

    float alpha = uq * uk;
    float gamma = cq * uk;
    float kk    = g * uv;
    float rr    = fmaf(Wf[e], bo[e], g * cv);

    #pragma unroll
    for (int off = 16; off; off >>= 1) {
        alpha += __shfl_xor_sync(0xffffffffu, alpha, off);
        gamma += __shfl_xor_sync(0xffffffffu, gamma, off);
        kk    += __shfl_xor_sync(0xffffffffu, kk, off);
        rr    += __shfl_xor_sync(0xffffffffu, rr, off);
    }
    if (e == 0) {
        const float inv_sqrtE = 0.17677669529663688f;  // 1/sqrt(32)
        g_C[w * 4 + 0] = alpha * inv_sqrtE;
        g_C[w * 4 + 1] = gamma * inv_sqrtE;
        g_C[w * 4 + 2] = 0.5f * kk;
        g_C[w * 4 + 3] = rr;
    }
}

// ---------------------------------------------------------------------------
// Main: each thread handles 4 batch elements (all loads/stores 16B-vectorized).
//   S_A = mean_i [ b0 + (b1-b0) * sigmoid((alpha*a_i + gamma) * (b1-b0)) ]
//   T_B = mean_j [ softmax-weighted mean of a over z_i = (alpha'*b_j + gamma')*a_i ]
//   y   = K0 + K1*S_A + K2*T_B ; leaky-relu(0.01)
// ---------------------------------------------------------------------------
__global__ void __launch_bounds__(256)
main_kernel(const float4* __restrict__ gA4, const float4* __restrict__ gB4,
            const float* __restrict__ bf, float4* __restrict__ out4, int nT)
{
    const int t = blockIdx.x * blockDim.x + threadIdx.x;
    if (t >= nT) return;

    const float C0 = g_C[0], C1 = g_C[1], C2 = g_C[2], C3 = g_C[3];
    const float C4 = g_C[4], C5 = g_C[5], C6 = g_C[6], C7 = g_C[7];
    const float K0 = fmaf(0.5f, C3 + C7, bf[0]);

    const float4 A0 = gA4[3 * t], A1 = gA4[3 * t + 1], A2 = gA4[3 * t + 2];
    const float4 B0 = gB4[2 * t], B1 = gB4[2 * t + 1];
    const float a[12] = {A0.x, A0.y, A0.z, A0.w, A1.x, A1.y, A1.z, A1.w,
                         A2.x, A2.y, A2.z, A2.w};
    const float b[8]  = {B0.x, B0.y, B0.z, B0.w, B1.x, B1.y, B1.z, B1.w};
    float r[4];

    #pragma unroll
    for (int q = 0; q < 4; ++q) {
        const float a0 = a[3 * q], a1 = a[3 * q + 1], a2 = a[3 * q + 2];
        const float b0 = b[2 * q], b1 = b[2 * q + 1];

        // AB direction: softmax over 2 kv tokens -> sigmoid
        const float db = b1 - b0;
        float S = 0.f;
        {
            const float l0 = fmaf(C0, a0, C1);
            const float l1 = fmaf(C0, a1, C1);
            const float l2 = fmaf(C0, a2, C1);
            const float s0 = __fdividef(1.f, 1.f + __expf(-l0 * db));
            const float s1 = __fdividef(1.f, 1.f + __expf(-l1 * db));
            const float s2 = __fdividef(1.f, 1.f + __expf(-l2 * db));
            S = fmaf(db, s0, b0) + fmaf(db, s1, b0) + fmaf(db, s2, b0);
            S *= (1.f / 3.f);
        }

        // BA direction: softmax over 3 kv tokens, for each of 2 queries
        float T = 0.f;
        #pragma unroll
        for (int j = 0; j < 2; ++j) {
            const float bj = (j == 0) ? b0 : b1;
            const float wj = fmaf(C4, bj, C5);
            const float z0 = wj * a0, z1 = wj * a1, z2 = wj * a2;
            const float m  = fmaxf(z0, fmaxf(z1, z2));
            const float e0 = __expf(z0 - m);
            const float e1 = __expf(z1 - m);
            const float e2 = __expf(z2 - m);
            T += __fdividef(fmaf(a0, e0, fmaf(a1, e1, a2 * e2)), e0 + e1 + e2);
        }
        T *= 0.5f;

        const float y = fmaf(C2, S, fmaf(C6, T, K0));
        r[q] = (y >= 0.f) ? y : 0.01f * y;
    }
    out4[t] = make_float4(r[0], r[1], r[2], r[3]);
}

// Scalar tail (only launched if B % 4 != 0; B=524288 so normally unused).
__global__ void tail_kernel(const float* __restrict__ gA, const float* __restrict__ gB,
                            const float* __restrict__ bf, float* __restrict__ out,
                            int start, int nB)
{
    const int idx = start + blockIdx.x * blockDim.x + threadIdx.x;
    if (idx >= nB) return;

    const float C0 = g_C[0], C1 = g_C[1], C2 = g_C[2], C3 = g_C[3];
    const float C4 = g_C[4], C5 = g_C[5], C6 = g_C[6], C7 = g_C[7];
    const float K0 = fmaf(0.5f, C3 + C7, bf[0]);

    const float a0 = gA[3 * idx], a1 = gA[3 * idx + 1], a2 = gA[3 * idx + 2];
    const float b0 = gB[2 * idx], b1 = gB[2 * idx + 1];

    const float db = b1 - b0;
    float S = 0.f;
    {
        const float l0 = fmaf(C0, a0, C1);
        const float l1 = fmaf(C0, a1, C1);
        const float l2 = fmaf(C0, a2, C1);
        S  = fmaf(db, __fdividef(1.f, 1.f + __expf(-l0 * db)), b0);
        S += fmaf(db, __fdividef(1.f, 1.f + __expf(-l1 * db)), b0);
        S += fmaf(db, __fdividef(1.f, 1.f + __expf(-l2 * db)), b0);
        S *= (1.f / 3.f);
    }
    float T = 0.f;
    for (int j = 0; j < 2; ++j) {
        const float bj = (j == 0) ? b0 : b1;
        const float wj = fmaf(C4, bj, C5);
        const float z0 = wj * a0, z1 = wj * a1, z2 = wj * a2;
        const float m  = fmaxf(z0, fmaxf(z1, z2));
        const float e0 = __expf(z0 - m), e1 = __expf(z1 - m), e2 = __expf(z2 - m);
        T += __fdividef(fmaf(a0, e0, fmaf(a1, e1, a2 * e2)), e0 + e1 + e2);
    }
    T *= 0.5f;
    const float y = fmaf(C2, S, fmaf(C6, T, K0));
    out[idx] = (y >= 0.f) ? y : 0.01f * y;
}

extern "C" void kernel_launch(void* const* d_in, const int* in_sizes, int n_in,
                              void* d_out, int out_size)
{
    const float* gA    = (const float*)d_in[0];   // [B,3]
    const float* gB    = (const float*)d_in[1];   // [B,2]
    const float* WA    = (const float*)d_in[2];   // [32,1]
    const float* bA    = (const float*)d_in[3];   // [32]
    const float* WB    = (const float*)d_in[4];
    const float* bB    = (const float*)d_in[5];
    const float* Wi_AB = (const float*)d_in[6];   // [96,32]
    const float* bi_AB = (const float*)d_in[7];   // [96]
    const float* Wo_AB = (const float*)d_in[8];   // [32,32]
    const float* bo_AB = (const float*)d_in[9];   // [32]
    const float* Wi_BA = (const float*)d_in[10];
    const float* bi_BA = (const float*)d_in[11];
    const float* Wo_BA = (const float*)d_in[12];
    const float* bo_BA = (const float*)d_in[13];
    const float* Wf    = (const float*)d_in[14];  // [1,32]
    const float* bf    = (const float*)d_in[15];  // [1]

    const int B = in_sizes[0] / 3;

    setup_kernel<<<1, 64>>>(WA, bA, WB, bB,
                            Wi_AB, bi_AB, Wo_AB, bo_AB,
                            Wi_BA, bi_BA, Wo_BA, bo_BA, Wf);

    const int nT = B / 4;
    if (nT > 0) {
        main_kernel<<<(nT + 255) / 256, 256>>>(
            (const float4*)gA, (const float4*)gB, bf, (float4*)d_out, nT);
    }
    const int rem = B - nT * 4;
    if (rem > 0) {
        tail_kernel<<<1, 256>>>(gA, gB, bf, (float*)d_out, nT * 4, B);
    }
}

// round 2
// speedup vs baseline: 1.1775x; 1.1775x over previous
#include <cuda_runtime.h>

// Derived scalar constants: [0..3]=AB {alpha,gamma,K1,R}, [4..7]=BA.
__device__ float g_C[8];

__device__ __forceinline__ float dot4(float4 x, float4 y) {
    return fmaf(x.x, y.x, fmaf(x.y, y.y, fmaf(x.z, y.z, x.w * y.w)));
}

// ---------------------------------------------------------------------------
// Setup: 2 warps, one per attention direction. Lane e computes component e of
// the derived vectors (vectorized float4 row loads), then warp-reduces.
// ---------------------------------------------------------------------------
__global__ void setup_kernel(
    const float* __restrict__ WA, const float* __restrict__ bA,
    const float* __restrict__ WB, const float* __restrict__ bB,
    const float* __restrict__ Wi_AB, const float* __restrict__ bi_AB,
    const float* __restrict__ Wo_AB, const float* __restrict__ bo_AB,
    const float* __restrict__ Wi_BA, const float* __restrict__ bi_BA,
    const float* __restrict__ Wo_BA, const float* __restrict__ bo_BA,
    const float* __restrict__ Wf)
{
    const int w = threadIdx.x >> 5;   // 0 = AB (q from A, kv from B), 1 = BA
    const int e = threadIdx.x & 31;
    if (w > 1) return;

    const float* Wi = w ? Wi_BA : Wi_AB;
    const float* bi = w ? bi_BA : bi_AB;
    const float* Wo = w ? Wo_BA : Wo_AB;
    const float* bo = w ? bo_BA : bo_AB;
    const float* q_w = w ? WB : WA;  const float* q_b = w ? bB : bA;
    const float* k_w = w ? WA : WB;  const float* k_b = w ? bA : bB;

    const float4* WiQ = (const float4*)(Wi + e * 32);
    const float4* WiK = (const float4*)(Wi + (32 + e) * 32);
    const float4* WiV = (const float4*)(Wi + (64 + e) * 32);
    const float4* QW  = (const float4*)q_w;
    const float4* QB  = (const float4*)q_b;
    const float4* KW  = (const float4*)k_w;
    const float4* KB  = (const float4*)k_b;

    float uq = 0.f, cq = 0.f, uk = 0.f, uv = 0.f, cv = 0.f, g = 0.f;
    #pragma unroll
    for (int i = 0; i < 8; ++i) {
        const float4 wq = WiQ[i], wk = WiK[i], wv = WiV[i];
        const float4 vqw = QW[i], vqb = QB[i], vkw = KW[i], vkb = KB[i];
        uq += dot4(wq, vqw);
        cq += dot4(wq, vqb);
        uk += dot4(wk, vkw);
        uv += dot4(wv, vkw);
        cv += dot4(wv, vkb);
    }
    #pragma unroll
    for (int d = 0; d < 32; ++d)
        g = fmaf(Wf[d], Wo[d * 32 + e], g);

    cq += bi[e];        // + bq[e]
    cv += bi[64 + e];   // + bv[e]

    float alpha = uq * uk;
    float gamma = cq * uk;
    float kk    = g * uv;
    float rr    = fmaf(Wf[e], bo[e], g * cv);

    #pragma unroll
    for (int off = 16; off; off >>= 1) {
        alpha += __shfl_xor_sync(0xffffffffu, alpha, off);
        gamma += __shfl_xor_sync(0xffffffffu, gamma, off);
        kk    += __shfl_xor_sync(0xffffffffu, kk, off);
        rr    += __shfl_xor_sync(0xffffffffu, rr, off);
    }
    if (e == 0) {
        const float inv_sqrtE = 0.17677669529663688f;  // 1/sqrt(32)
        g_C[w * 4 + 0] = alpha * inv_sqrtE;
        g_C[w * 4 + 1] = gamma * inv_sqrtE;
        g_C[w * 4 + 2] = 0.5f * kk;
        g_C[w * 4 + 3] = rr;
    }
}

// ---------------------------------------------------------------------------
// Main: 2 batch elements per thread (all loads/stores vectorized+aligned).
// ---------------------------------------------------------------------------
__global__ void __launch_bounds__(256)
main_kernel(const float2* __restrict__ gA2, const float4* __restrict__ gB4,
            const float* __restrict__ bf, float2* __restrict__ out2, int nT)
{
    const int t = blockIdx.x * blockDim.x + threadIdx.x;
    if (t >= nT) return;

    const float C0 = g_C[0], C1 = g_C[1], C2 = g_C[2], C3 = g_C[3];
    const float C4 = g_C[4], C5 = g_C[5], C6 = g_C[6], C7 = g_C[7];
    const float K0 = fmaf(0.5f, C3 + C7, bf[0]);

    // elements 2t, 2t+1: gA floats [6t..6t+5], gB floats [4t..4t+3]
    const float2 A0 = gA2[3 * t], A1 = gA2[3 * t + 1], A2 = gA2[3 * t + 2];
    const float4 Bv = gB4[t];
    const float a[6] = {A0.x, A0.y, A1.x, A1.y, A2.x, A2.y};
    const float b[4] = {Bv.x, Bv.y, Bv.z, Bv.w};
    float r[2];

    #pragma unroll
    for (int q = 0; q < 2; ++q) {
        const float a0 = a[3 * q], a1 = a[3 * q + 1], a2 = a[3 * q + 2];
        const float b0 = b[2 * q], b1 = b[2 * q + 1];

        // AB direction: softmax over 2 kv tokens -> sigmoid
        const float db = b1 - b0;
        float S;
        {
            const float l0 = fmaf(C0, a0, C1);
            const float l1 = fmaf(C0, a1, C1);
            const float l2 = fmaf(C0, a2, C1);
            const float s0 = __fdividef(1.f, 1.f + __expf(-l0 * db));
            const float s1 = __fdividef(1.f, 1.f + __expf(-l1 * db));
            const float s2 = __fdividef(1.f, 1.f + __expf(-l2 * db));
            S = (fmaf(db, s0, b0) + fmaf(db, s1, b0) + fmaf(db, s2, b0))
                * (1.f / 3.f);
        }

        // BA direction: softmax over 3 kv tokens, for each of 2 queries
        float T = 0.f;
        #pragma unroll
        for (int j = 0; j < 2; ++j) {
            const float bj = (j == 0) ? b0 : b1;
            const float wj = fmaf(C4, bj, C5);
            const float z0 = wj * a0, z1 = wj * a1, z2 = wj * a2;
            const float m  = fmaxf(z0, fmaxf(z1, z2));
            const float e0 = __expf(z0 - m);
            const float e1 = __expf(z1 - m);
            const float e2 = __expf(z2 - m);
            T += __fdividef(fmaf(a0, e0, fmaf(a1, e1, a2 * e2)), e0 + e1 + e2);
        }
        T *= 0.5f;

        const float y = fmaf(C2, S, fmaf(C6, T, K0));
        r[q] = (y >= 0.f) ? y : 0.01f * y;
    }
    out2[t] = make_float2(r[0], r[1]);
}

// Scalar tail (only launched if B % 2 != 0; B=524288 so normally unused).
__global__ void tail_kernel(const float* __restrict__ gA, const float* __restrict__ gB,
                            const float* __restrict__ bf, float* __restrict__ out,
                            int start, int nB)
{
    const int idx = start + blockIdx.x * blockDim.x + threadIdx.x;
    if (idx >= nB) return;

    const float C0 = g_C[0], C1 = g_C[1], C2 = g_C[2], C3 = g_C[3];
    const float C4 = g_C[4], C5 = g_C[5], C6 = g_C[6], C7 = g_C[7];
    const float K0 = fmaf(0.5f, C3 + C7, bf[0]);

    const float a0 = gA[3 * idx], a1 = gA[3 * idx + 1], a2 = gA[3 * idx + 2];
    const float b0 = gB[2 * idx], b1 = gB[2 * idx + 1];

    const float db = b1 - b0;
    float S;
    {
        const float l0 = fmaf(C0, a0, C1);
        const float l1 = fmaf(C0, a1, C1);
        const float l2 = fmaf(C0, a2, C1);
        S  = fmaf(db, __fdividef(1.f, 1.f + __expf(-l0 * db)), b0);
        S += fmaf(db, __fdividef(1.f, 1.f + __expf(-l1 * db)), b0);
        S += fmaf(db, __fdividef(1.f, 1.f + __expf(-l2 * db)), b0);
        S *= (1.f / 3.f);
    }
    float T = 0.f;
    for (int j = 0; j < 2; ++j) {
        const float bj = (j == 0) ? b0 : b1;
        const float wj = fmaf(C4, bj, C5);
        const float z0 = wj * a0, z1 = wj * a1, z2 = wj * a2;
        const float m  = fmaxf(z0, fmaxf(z1, z2));
        const float e0 = __expf(z0 - m), e1 = __expf(z1 - m), e2 = __expf(z2 - m);
        T += __fdividef(fmaf(a0, e0, fmaf(a1, e1, a2 * e2)), e0 + e1 + e2);
    }
    T *= 0.5f;
    const float y = fmaf(C2, S, fmaf(C6, T, K0));
    out[idx] = (y >= 0.f) ? y : 0.01f * y;
}

extern "C" void kernel_launch(void* const* d_in, const int* in_sizes, int n_in,
                              void* d_out, int out_size)
{
    const float* gA    = (const float*)d_in[0];   // [B,3]
    const float* gB    = (const float*)d_in[1];   // [B,2]
    const float* WA    = (const float*)d_in[2];   // [32,1]
    const float* bA    = (const float*)d_in[3];   // [32]
    const float* WB    = (const float*)d_in[4];
    const float* bB    = (const float*)d_in[5];
    const float* Wi_AB = (const float*)d_in[6];   // [96,32]
    const float* bi_AB = (const float*)d_in[7];   // [96]
    const float* Wo_AB = (const float*)d_in[8];   // [32,32]
    const float* bo_AB = (const float*)d_in[9];   // [32]
    const float* Wi_BA = (const float*)d_in[10];
    const float* bi_BA = (const float*)d_in[11];
    const float* Wo_BA = (const float*)d_in[12];
    const float* bo_BA = (const float*)d_in[13];
    const float* Wf    = (const float*)d_in[14];  // [1,32]
    const float* bf    = (const float*)d_in[15];  // [1]

    const int B = in_sizes[0] / 3;

    setup_kernel<<<1, 64>>>(WA, bA, WB, bB,
                            Wi_AB, bi_AB, Wo_AB, bo_AB,
                            Wi_BA, bi_BA, Wo_BA, bo_BA, Wf);

    const int nT = B / 2;
    if (nT > 0) {
        main_kernel<<<(nT + 255) / 256, 256>>>(
            (const float2*)gA, (const float4*)gB, bf, (float2*)d_out, nT);
    }
    const int rem = B - nT * 2;
    if (rem > 0) {
        tail_kernel<<<1, 256>>>(gA, gB, bf, (float*)d_out, nT * 2, B);
    }
}